// round 7
// baseline (speedup 1.0000x reference)
#include <cuda_runtime.h>
#include <cuda_bf16.h>
#include <math.h>
#include <stdint.h>

#define BB 64
#define TT 31
#define EE 512
#define HH 1024
#define GG 4096
#define VV 32000
#define MPAD 2048
typedef __nv_bfloat16 bf;

__device__ __align__(16) bf g_linWH[(size_t)VV * HH], g_linWL[(size_t)VV * HH];
__device__ __align__(16) bf g_WihH[(size_t)GG * 1536], g_WihL[(size_t)GG * 1536];
__device__ __align__(16) bf g_WhhH[(size_t)GG * HH], g_WhhL[(size_t)GG * HH];
__device__ __align__(16) bf g_ctxH[BB * HH], g_ctxL[BB * HH];
__device__ __align__(16) bf g_embH[(size_t)TT * BB * EE], g_embL[(size_t)TT * BB * EE];
__device__ __align__(16) bf g_hsH[(size_t)MPAD * HH], g_hsL[(size_t)MPAD * HH];
__device__ __align__(16) bf g_h0H[BB * HH], g_h0L[BB * HH];
__device__ float g_gbias[BB * GG];
__device__ float g_gx[(size_t)TT * BB * GG];
__device__ float g_c[BB * HH];

// ---------------------------------------------------------------------------
#define CP16(dst, src) asm volatile("cp.async.ca.shared.global [%0], [%1], 16;" :: "r"(dst), "l"(src) : "memory")
#define CP_COMMIT() asm volatile("cp.async.commit_group;" ::: "memory")
#define CP_WAIT0() asm volatile("cp.async.wait_group 0;" ::: "memory")
#define CP_WAIT3() asm volatile("cp.async.wait_group 3;" ::: "memory")

__device__ __forceinline__ unsigned s2u(const void* p) {
    return (unsigned)__cvta_generic_to_shared(p);
}
__device__ __forceinline__ void mma_bf16(float c[4], const unsigned a[4], const unsigned b[2]) {
    asm("mma.sync.aligned.m16n8k16.row.col.f32.bf16.bf16.f32 "
        "{%0,%1,%2,%3},{%4,%5,%6,%7},{%8,%9},{%0,%1,%2,%3};"
        : "+f"(c[0]), "+f"(c[1]), "+f"(c[2]), "+f"(c[3])
        : "r"(a[0]), "r"(a[1]), "r"(a[2]), "r"(a[3]), "r"(b[0]), "r"(b[1]));
}
__device__ __forceinline__ void split2(float x, float y, unsigned& hi, unsigned& lo) {
    bf hx = __float2bfloat16(x), hy = __float2bfloat16(y);
    __nv_bfloat162 H = __halves2bfloat162(hx, hy);
    __nv_bfloat162 L = __halves2bfloat162(__float2bfloat16(x - __bfloat162float(hx)),
                                          __float2bfloat16(y - __bfloat162float(hy)));
    hi = *(unsigned*)&H;
    lo = *(unsigned*)&L;
}

// ---------------------------------------------------------------------------
__global__ void k_init() {
    int i = blockIdx.x * blockDim.x + threadIdx.x;
    if (i < BB * HH) {
        g_h0H[i] = __float2bfloat16(0.f);
        g_h0L[i] = __float2bfloat16(0.f);
        g_c[i] = 0.f;
    }
    if (i < (MPAD - TT * BB) * HH) {
        size_t p = (size_t)TT * BB * HH + i;
        g_hsH[p] = __float2bfloat16(0.f);
        g_hsL[p] = __float2bfloat16(0.f);
    }
}

__global__ void k_conv(const float4* __restrict__ S, uint2* __restrict__ H,
                       uint2* __restrict__ L, int n4) {
    int i = blockIdx.x * blockDim.x + threadIdx.x;
    if (i >= n4) return;
    float4 v = S[i];
    uint2 h, l;
    split2(v.x, v.y, h.x, l.x);
    split2(v.z, v.w, h.y, l.y);
    H[i] = h;
    L[i] = l;
}

__global__ void k_ctx(const float* __restrict__ features) {
    int b = blockIdx.x;
    for (int h = threadIdx.x; h < HH; h += blockDim.x) {
        const float* p = features + (size_t)b * 64 * HH + h;
        float s = 0.f;
#pragma unroll 8
        for (int l = 0; l < 64; l++) s += p[(size_t)l * HH];
        bf hi = __float2bfloat16(s);
        g_ctxH[b * HH + h] = hi;
        g_ctxL[b * HH + h] = __float2bfloat16(s - __bfloat162float(hi));
    }
}

__global__ void k_emb(const float* __restrict__ embed, const int* __restrict__ captions) {
    int v = blockIdx.x * blockDim.x + threadIdx.x;
    int m = v >> 7;
    int e4 = (v & 127) << 2;
    int t = m / 64, b = m % 64;
    int cap = captions[b * 32 + t];
    float4 val = *(const float4*)(embed + (size_t)cap * EE + e4);
    uint2 h, l;
    split2(val.x, val.y, h.x, l.x);
    split2(val.z, val.w, h.y, l.y);
    ((uint2*)g_embH)[((size_t)m * EE + e4) >> 2] = h;
    ((uint2*)g_embL)[((size_t)m * EE + e4) >> 2] = l;
}

// ---------------------------------------------------------------------------
// mma.sync bf16x3 GEMM for the small gbias/gx GEMMs (BM=64, BN=128, 2-stage).
template<int MODE>
__global__ __launch_bounds__(256) void k_mm(
    const bf* __restrict__ AH, const bf* __restrict__ AL, int lda,
    const bf* __restrict__ BH, const bf* __restrict__ BL, int ldb,
    float* __restrict__ C, int ldc, int K,
    const float* __restrict__ bias1, const float* __restrict__ bias2,
    const float* __restrict__ addM)
{
    __shared__ unsigned AsH[2][64][12], AsL[2][64][12];
    __shared__ unsigned BsH[2][128][12], BsL[2][128][12];
    const int tid = threadIdx.x;
    const int wid = tid >> 5, lane = tid & 31, g = lane >> 2, tig = lane & 3;
    const int wm = (wid & 1) * 32, wn = (wid >> 1) * 32;
    const int bm = blockIdx.y * 64, bn = blockIdx.x * 128;

    const int arow = tid >> 2, asel = (tid >> 1) & 1, achk = tid & 1;
    const bf* aSrc = (asel ? AL : AH) + (size_t)(bm + arow) * lda + achk * 8;
    unsigned aD[2] = { s2u(&(asel ? AsL : AsH)[0][arow][achk * 4]),
                       s2u(&(asel ? AsL : AsH)[1][arow][achk * 4]) };
    const int b0r = tid >> 2, b0s = (tid >> 1) & 1, b0c = tid & 1;
    const int id1 = tid + 256;
    const int b1r = id1 >> 2, b1s = (id1 >> 1) & 1, b1c = id1 & 1;
    const bf* bSrc0 = (b0s ? BL : BH) + (size_t)(bn + b0r) * ldb + b0c * 8;
    const bf* bSrc1 = (b1s ? BL : BH) + (size_t)(bn + b1r) * ldb + b1c * 8;
    unsigned b0D[2] = { s2u(&(b0s ? BsL : BsH)[0][b0r][b0c * 4]),
                        s2u(&(b0s ? BsL : BsH)[1][b0r][b0c * 4]) };
    unsigned b1D[2] = { s2u(&(b1s ? BsL : BsH)[0][b1r][b1c * 4]),
                        s2u(&(b1s ? BsL : BsH)[1][b1r][b1c * 4]) };

    float acc[2][4][4] = {};
    CP16(aD[0], aSrc); CP16(b0D[0], bSrc0); CP16(b1D[0], bSrc1); CP_COMMIT();

    const int KT = K >> 4;
    for (int kt = 0; kt < KT; kt++) {
        const int cur = kt & 1, nxt = cur ^ 1;
        CP_WAIT0();
        __syncthreads();
        if (kt + 1 < KT) {
            CP16(aD[nxt], aSrc + (kt + 1) * 16);
            CP16(b0D[nxt], bSrc0 + (kt + 1) * 16);
            CP16(b1D[nxt], bSrc1 + (kt + 1) * 16);
            CP_COMMIT();
        }
        unsigned afH[2][4], afL[2][4], bfH[4][2], bfL[4][2];
#pragma unroll
        for (int mt = 0; mt < 2; mt++) {
            int r = wm + mt * 16 + g;
            afH[mt][0] = AsH[cur][r][tig];     afH[mt][1] = AsH[cur][r + 8][tig];
            afH[mt][2] = AsH[cur][r][tig + 4]; afH[mt][3] = AsH[cur][r + 8][tig + 4];
            afL[mt][0] = AsL[cur][r][tig];     afL[mt][1] = AsL[cur][r + 8][tig];
            afL[mt][2] = AsL[cur][r][tig + 4]; afL[mt][3] = AsL[cur][r + 8][tig + 4];
        }
#pragma unroll
        for (int nt = 0; nt < 4; nt++) {
            int n = wn + nt * 8 + g;
            bfH[nt][0] = BsH[cur][n][tig]; bfH[nt][1] = BsH[cur][n][tig + 4];
            bfL[nt][0] = BsL[cur][n][tig]; bfL[nt][1] = BsL[cur][n][tig + 4];
        }
#pragma unroll
        for (int mt = 0; mt < 2; mt++)
#pragma unroll
            for (int nt = 0; nt < 4; nt++) {
                mma_bf16(acc[mt][nt], afL[mt], bfH[nt]);
                mma_bf16(acc[mt][nt], afH[mt], bfL[nt]);
                mma_bf16(acc[mt][nt], afH[mt], bfH[nt]);
            }
    }

#pragma unroll
    for (int mt = 0; mt < 2; mt++) {
#pragma unroll
        for (int nt = 0; nt < 4; nt++) {
            int r0 = bm + wm + mt * 16 + g, r1 = r0 + 8;
            int n0 = bn + wn + nt * 8 + 2 * tig;
            float2 v01 = make_float2(acc[mt][nt][0], acc[mt][nt][1]);
            float2 v23 = make_float2(acc[mt][nt][2], acc[mt][nt][3]);
            if (MODE == 0) {
                float2 x = *(const float2*)(bias1 + n0);
                float2 y = *(const float2*)(bias2 + n0);
                v01.x += x.x + y.x; v01.y += x.y + y.y;
                v23.x += x.x + y.x; v23.y += x.y + y.y;
            }
            if (MODE == 1) {
                float2 x = *(const float2*)(addM + (size_t)(r0 & 63) * GG + n0);
                float2 y = *(const float2*)(addM + (size_t)(r1 & 63) * GG + n0);
                v01.x += x.x; v01.y += x.y;
                v23.x += y.x; v23.y += y.y;
            }
            *(float2*)(C + (size_t)r0 * ldc + n0) = v01;
            *(float2*)(C + (size_t)r1 * ldc + n0) = v23;
        }
    }
}

// ---------------------------------------------------------------------------
// Recurrent step: gates(64x32) = h(t-1) @ W_hh perm, fused LSTM pointwise.
__global__ __launch_bounds__(256) void k_step(const bf* __restrict__ AH,
                                              const bf* __restrict__ AL, int t) {
    __shared__ unsigned AsH[2][64][12], AsL[2][64][12];
    __shared__ unsigned BsH[2][32][12], BsL[2][32][12];
    __shared__ float sg[64][33];
    const int tid = threadIdx.x;
    const int wid = tid >> 5, lane = tid & 31, g = lane >> 2, tig = lane & 3;
    const int wm = (wid & 1) * 32, wn = (wid >> 1) * 8;
    const int jj0 = blockIdx.x * 8;

    const int arow = tid >> 2, asel = (tid >> 1) & 1, achk = tid & 1;
    const bf* aSrc = (asel ? AL : AH) + (size_t)arow * HH + achk * 8;
    unsigned aD[2] = { s2u(&(asel ? AsL : AsH)[0][arow][achk * 4]),
                       s2u(&(asel ? AsL : AsH)[1][arow][achk * 4]) };
    const bf* bSrc = nullptr;
    unsigned bD[2] = {0, 0};
    if (tid < 128) {
        int br = tid >> 2, bs = (tid >> 1) & 1, bc = tid & 1;
        int wrow = (br >> 3) * HH + jj0 + (br & 7);
        bSrc = (bs ? g_WhhL : g_WhhH) + (size_t)wrow * HH + bc * 8;
        bD[0] = s2u(&(bs ? BsL : BsH)[0][br][bc * 4]);
        bD[1] = s2u(&(bs ? BsL : BsH)[1][br][bc * 4]);
    }

    float acc[2][4] = {};
    CP16(aD[0], aSrc);
    if (tid < 128) CP16(bD[0], bSrc);
    CP_COMMIT();

    const int KT = HH >> 4;
    for (int kt = 0; kt < KT; kt++) {
        const int cur = kt & 1, nxt = cur ^ 1;
        CP_WAIT0();
        __syncthreads();
        if (kt + 1 < KT) {
            CP16(aD[nxt], aSrc + (kt + 1) * 16);
            if (tid < 128) CP16(bD[nxt], bSrc + (kt + 1) * 16);
            CP_COMMIT();
        }
        unsigned afH[2][4], afL[2][4], bfH[2], bfL[2];
#pragma unroll
        for (int mt = 0; mt < 2; mt++) {
            int r = wm + mt * 16 + g;
            afH[mt][0] = AsH[cur][r][tig];     afH[mt][1] = AsH[cur][r + 8][tig];
            afH[mt][2] = AsH[cur][r][tig + 4]; afH[mt][3] = AsH[cur][r + 8][tig + 4];
            afL[mt][0] = AsL[cur][r][tig];     afL[mt][1] = AsL[cur][r + 8][tig];
            afL[mt][2] = AsL[cur][r][tig + 4]; afL[mt][3] = AsL[cur][r + 8][tig + 4];
        }
        int n = wn + g;
        bfH[0] = BsH[cur][n][tig]; bfH[1] = BsH[cur][n][tig + 4];
        bfL[0] = BsL[cur][n][tig]; bfL[1] = BsL[cur][n][tig + 4];
#pragma unroll
        for (int mt = 0; mt < 2; mt++) {
            mma_bf16(acc[mt], afL[mt], bfH);
            mma_bf16(acc[mt], afH[mt], bfL);
            mma_bf16(acc[mt], afH[mt], bfH);
        }
    }

#pragma unroll
    for (int mt = 0; mt < 2; mt++)
#pragma unroll
        for (int q = 0; q < 4; q++) {
            int r = wm + mt * 16 + g + ((q >> 1) * 8);
            int j = wn + 2 * tig + (q & 1);
            sg[r][j] = acc[mt][q];
        }
    __syncthreads();

    const float* __restrict__ gx = g_gx + (size_t)t * 64 * GG;
    for (int u = tid; u < 512; u += 256) {
        int b = u >> 3, hh = u & 7;
        size_t gbase = (size_t)b * GG + jj0 + hh;
        float gi = sg[b][0 * 8 + hh] + gx[gbase];
        float gf = sg[b][1 * 8 + hh] + gx[gbase + HH];
        float gg = sg[b][2 * 8 + hh] + gx[gbase + 2 * HH];
        float go = sg[b][3 * 8 + hh] + gx[gbase + 3 * HH];
        int ci = b * HH + jj0 + hh;
        float cOld = g_c[ci];
        float si = 1.f / (1.f + expf(-gi));
        float sf = 1.f / (1.f + expf(-gf));
        float so = 1.f / (1.f + expf(-go));
        float cN = sf * cOld + si * tanhf(gg);
        float hN = so * tanhf(cN);
        g_c[ci] = cN;
        size_t hidx = ((size_t)t * 64 + b) * HH + jj0 + hh;
        bf hb = __float2bfloat16(hN);
        g_hsH[hidx] = hb;
        g_hsL[hidx] = __float2bfloat16(hN - __bfloat162float(hb));
    }
}

// ---------------------------------------------------------------------------
// Logits GEMM: out[m,v] = sum_k hs[m,k]*lin_W[v,k] + lin_b[v]
// BM=128, BN=256, BK=16, 8 warps, warp tile 64x64, 4-stage cp.async pipeline.
// Stage layout (uint words): AH[128][12] @0 | AL @1536 | BH[256][12] @3072 | BL @6144
#define STG_W 9216                 // words per stage (36 KB)
#define SMEM_LG (4 * STG_W * 4)    // 144 KB

__global__ __launch_bounds__(256, 1) void k_logits2(const float* __restrict__ lin_b,
                                                    float* __restrict__ out) {
    extern __shared__ unsigned sm[];
    const int tid = threadIdx.x;
    const int wid = tid >> 5, lane = tid & 31, g = lane >> 2, tig = lane & 3;
    const int wm = (wid & 1) * 64, wn = (wid >> 1) * 64;
    const int bm = blockIdx.x * 128, bn = blockIdx.y * 256;

    // per-thread copy task decode (6 x 16B per slab)
    int crow[6], cword[6];
    const bf* csrc[6];
#pragma unroll
    for (int q = 0; q < 6; q++) {
        int i = tid + q * 256;
        if (i < 512) {
            int row = i >> 2, sel = (i >> 1) & 1, chunk = i & 1;
            csrc[q] = (sel ? g_hsL : g_hsH) + (size_t)(bm + row) * HH + chunk * 8;
            cword[q] = sel * 1536 + row * 12 + chunk * 4;
        } else {
            int j = i - 512;
            int row = j >> 2, sel = (j >> 1) & 1, chunk = j & 1;
            csrc[q] = (sel ? g_linWL : g_linWH) + (size_t)(bn + row) * HH + chunk * 8;
            cword[q] = 3072 + sel * 3072 + row * 12 + chunk * 4;
        }
    }

    float acc[4][8][4] = {};

    // prologue: prefetch slabs 0..2
#pragma unroll
    for (int s = 0; s < 3; s++) {
#pragma unroll
        for (int q = 0; q < 6; q++)
            CP16(s2u(&sm[s * STG_W + cword[q]]), csrc[q] + s * 16);
        CP_COMMIT();
    }

    const int KT = HH >> 4;   // 64 slabs
    for (int kt = 0; kt < KT; kt++) {
        if (kt + 3 < KT) {
            int s = (kt + 3) & 3;
#pragma unroll
            for (int q = 0; q < 6; q++)
                CP16(s2u(&sm[s * STG_W + cword[q]]), csrc[q] + (kt + 3) * 16);
        }
        CP_COMMIT();          // may be empty; keeps group count uniform
        CP_WAIT3();
        __syncthreads();

        const unsigned* AHs = sm + (kt & 3) * STG_W;
        const unsigned* ALs = AHs + 1536;
        const unsigned* BHs = AHs + 3072;
        const unsigned* BLs = AHs + 6144;

        unsigned aH[4][4], aL[4][4];
#pragma unroll
        for (int mt = 0; mt < 4; mt++) {
            int r = (wm + mt * 16 + g) * 12;
            aH[mt][0] = AHs[r + tig];          aH[mt][1] = AHs[r + 96 + tig];
            aH[mt][2] = AHs[r + tig + 4];      aH[mt][3] = AHs[r + 96 + tig + 4];
            aL[mt][0] = ALs[r + tig];          aL[mt][1] = ALs[r + 96 + tig];
            aL[mt][2] = ALs[r + tig + 4];      aL[mt][3] = ALs[r + 96 + tig + 4];
        }
#pragma unroll
        for (int nt = 0; nt < 8; nt++) {
            int n = (wn + nt * 8 + g) * 12;
            unsigned bH[2], bL[2];
            bH[0] = BHs[n + tig]; bH[1] = BHs[n + tig + 4];
            bL[0] = BLs[n + tig]; bL[1] = BLs[n + tig + 4];
#pragma unroll
            for (int mt = 0; mt < 4; mt++) {
                mma_bf16(acc[mt][nt], aL[mt], bH);
                mma_bf16(acc[mt][nt], aH[mt], bL);
                mma_bf16(acc[mt][nt], aH[mt], bH);
            }
        }
        __syncthreads();
    }

    // epilogue
#pragma unroll
    for (int mt = 0; mt < 4; mt++) {
#pragma unroll
        for (int q2 = 0; q2 < 2; q2++) {
            int m = bm + wm + mt * 16 + g + q2 * 8;
            if (m >= TT * BB) continue;
            float* orow = out + (size_t)m * VV + bn;
#pragma unroll
            for (int nt = 0; nt < 8; nt++) {
                int n0 = wn + nt * 8 + 2 * tig;
                float2 bb = *(const float2*)(lin_b + bn + n0);
                float2 v = make_float2(acc[mt][nt][q2 * 2] + bb.x,
                                       acc[mt][nt][q2 * 2 + 1] + bb.y);
                *(float2*)(orow + n0) = v;
            }
        }
    }
}

// ---------------------------------------------------------------------------
extern "C" void kernel_launch(void* const* d_in, const int* in_sizes, int n_in,
                              void* d_out, int out_size) {
    const float* features = (const float*)d_in[0];
    const int*   captions = (const int*)d_in[1];
    const float* embed    = (const float*)d_in[3];
    const float* W_ih     = (const float*)d_in[4];
    const float* W_hh     = (const float*)d_in[5];
    const float* b_ih     = (const float*)d_in[6];
    const float* b_hh     = (const float*)d_in[7];
    const float* lin_W    = (const float*)d_in[10];
    const float* lin_b    = (const float*)d_in[11];
    float* out = (float*)d_out;

    bf *p_linWH, *p_linWL, *p_WihH, *p_WihL, *p_WhhH, *p_WhhL;
    bf *p_ctxH, *p_ctxL, *p_embH, *p_embL, *p_hsH, *p_hsL, *p_h0H, *p_h0L;
    float *p_gbias, *p_gx;
    cudaGetSymbolAddress((void**)&p_linWH, g_linWH);
    cudaGetSymbolAddress((void**)&p_linWL, g_linWL);
    cudaGetSymbolAddress((void**)&p_WihH, g_WihH);
    cudaGetSymbolAddress((void**)&p_WihL, g_WihL);
    cudaGetSymbolAddress((void**)&p_WhhH, g_WhhH);
    cudaGetSymbolAddress((void**)&p_WhhL, g_WhhL);
    cudaGetSymbolAddress((void**)&p_ctxH, g_ctxH);
    cudaGetSymbolAddress((void**)&p_ctxL, g_ctxL);
    cudaGetSymbolAddress((void**)&p_embH, g_embH);
    cudaGetSymbolAddress((void**)&p_embL, g_embL);
    cudaGetSymbolAddress((void**)&p_hsH, g_hsH);
    cudaGetSymbolAddress((void**)&p_hsL, g_hsL);
    cudaGetSymbolAddress((void**)&p_h0H, g_h0H);
    cudaGetSymbolAddress((void**)&p_h0L, g_h0L);
    cudaGetSymbolAddress((void**)&p_gbias, g_gbias);
    cudaGetSymbolAddress((void**)&p_gx, g_gx);

    cudaFuncSetAttribute(k_logits2, cudaFuncAttributeMaxDynamicSharedMemorySize, SMEM_LG);

    k_init<<<(BB * HH + 255) / 256, 256>>>();
    int n4;
    n4 = VV * HH / 4;
    k_conv<<<(n4 + 255) / 256, 256>>>((const float4*)lin_W, (uint2*)p_linWH, (uint2*)p_linWL, n4);
    n4 = GG * 1536 / 4;
    k_conv<<<(n4 + 255) / 256, 256>>>((const float4*)W_ih, (uint2*)p_WihH, (uint2*)p_WihL, n4);
    n4 = GG * HH / 4;
    k_conv<<<(n4 + 255) / 256, 256>>>((const float4*)W_hh, (uint2*)p_WhhH, (uint2*)p_WhhL, n4);
    k_ctx<<<BB, 256>>>(features);
    k_emb<<<(TT * BB * EE / 4 + 255) / 256, 256>>>(embed, captions);
    k_mm<0><<<dim3(GG / 128, 1), 256>>>(p_ctxH, p_ctxL, HH,
                                        p_WihH + 512, p_WihL + 512, 1536,
                                        p_gbias, GG, HH, b_ih, b_hh, nullptr);
    k_mm<1><<<dim3(GG / 128, TT), 256>>>(p_embH, p_embL, EE,
                                         p_WihH, p_WihL, 1536,
                                         p_gx, GG, EE, nullptr, nullptr, p_gbias);
    for (int t = 0; t < TT; t++) {
        const bf* AH = t ? p_hsH + (size_t)(t - 1) * BB * HH : p_h0H;
        const bf* AL = t ? p_hsL + (size_t)(t - 1) * BB * HH : p_h0L;
        k_step<<<128, 256>>>(AH, AL, t);
    }
    k_logits2<<<dim3(MPAD / 128, VV / 256), 256, SMEM_LG>>>(lin_b, out);
}

// round 8
// speedup vs baseline: 1.6285x; 1.6285x over previous
#include <cuda_runtime.h>
#include <cuda_bf16.h>
#include <math.h>
#include <stdint.h>

#define BB 64
#define TT 31
#define EE 512
#define HH 1024
#define GG 4096
#define VV 32000
#define MPAD 2048
typedef __nv_bfloat16 bf;

__device__ __align__(16) bf g_linWH[(size_t)VV * HH], g_linWL[(size_t)VV * HH];
__device__ __align__(16) bf g_WihH[(size_t)GG * 1536], g_WihL[(size_t)GG * 1536];
__device__ __align__(16) bf g_WhhH[(size_t)GG * HH], g_WhhL[(size_t)GG * HH];
__device__ __align__(16) bf g_ctxH[BB * HH], g_ctxL[BB * HH];
__device__ __align__(16) bf g_embH[(size_t)TT * BB * EE], g_embL[(size_t)TT * BB * EE];
__device__ __align__(16) bf g_hsH[(size_t)MPAD * HH], g_hsL[(size_t)MPAD * HH];
__device__ __align__(16) bf g_h0H[BB * HH], g_h0L[BB * HH];
__device__ float g_gbias[BB * GG];
__device__ float g_gx[(size_t)TT * BB * GG];
__device__ float g_c[BB * HH];

// ---------------------------------------------------------------------------
#define CP16(dst, src) asm volatile("cp.async.ca.shared.global [%0], [%1], 16;" :: "r"(dst), "l"(src) : "memory")
#define CP_COMMIT() asm volatile("cp.async.commit_group;" ::: "memory")
#define CP_WAIT0() asm volatile("cp.async.wait_group 0;" ::: "memory")
#define CP_WAIT1() asm volatile("cp.async.wait_group 1;" ::: "memory")

__device__ __forceinline__ unsigned s2u(const void* p) {
    return (unsigned)__cvta_generic_to_shared(p);
}
__device__ __forceinline__ void mma_bf16(float c[4], const unsigned a[4], const unsigned b[2]) {
    asm("mma.sync.aligned.m16n8k16.row.col.f32.bf16.bf16.f32 "
        "{%0,%1,%2,%3},{%4,%5,%6,%7},{%8,%9},{%0,%1,%2,%3};"
        : "+f"(c[0]), "+f"(c[1]), "+f"(c[2]), "+f"(c[3])
        : "r"(a[0]), "r"(a[1]), "r"(a[2]), "r"(a[3]), "r"(b[0]), "r"(b[1]));
}
__device__ __forceinline__ void split2(float x, float y, unsigned& hi, unsigned& lo) {
    bf hx = __float2bfloat16(x), hy = __float2bfloat16(y);
    __nv_bfloat162 H = __halves2bfloat162(hx, hy);
    __nv_bfloat162 L = __halves2bfloat162(__float2bfloat16(x - __bfloat162float(hx)),
                                          __float2bfloat16(y - __bfloat162float(hy)));
    hi = *(unsigned*)&H;
    lo = *(unsigned*)&L;
}

// ---------------------------------------------------------------------------
__global__ void k_init() {
    int i = blockIdx.x * blockDim.x + threadIdx.x;
    if (i < BB * HH) {
        g_h0H[i] = __float2bfloat16(0.f);
        g_h0L[i] = __float2bfloat16(0.f);
        g_c[i] = 0.f;
    }
    if (i < (MPAD - TT * BB) * HH) {
        size_t p = (size_t)TT * BB * HH + i;
        g_hsH[p] = __float2bfloat16(0.f);
        g_hsL[p] = __float2bfloat16(0.f);
    }
}

__global__ void k_conv(const float4* __restrict__ S, uint2* __restrict__ H,
                       uint2* __restrict__ L, int n4) {
    int i = blockIdx.x * blockDim.x + threadIdx.x;
    if (i >= n4) return;
    float4 v = S[i];
    uint2 h, l;
    split2(v.x, v.y, h.x, l.x);
    split2(v.z, v.w, h.y, l.y);
    H[i] = h;
    L[i] = l;
}

__global__ void k_ctx(const float* __restrict__ features) {
    int b = blockIdx.x;
    for (int h = threadIdx.x; h < HH; h += blockDim.x) {
        const float* p = features + (size_t)b * 64 * HH + h;
        float s = 0.f;
#pragma unroll 8
        for (int l = 0; l < 64; l++) s += p[(size_t)l * HH];
        bf hi = __float2bfloat16(s);
        g_ctxH[b * HH + h] = hi;
        g_ctxL[b * HH + h] = __float2bfloat16(s - __bfloat162float(hi));
    }
}

__global__ void k_emb(const float* __restrict__ embed, const int* __restrict__ captions) {
    int v = blockIdx.x * blockDim.x + threadIdx.x;
    int m = v >> 7;
    int e4 = (v & 127) << 2;
    int t = m / 64, b = m % 64;
    int cap = captions[b * 32 + t];
    float4 val = *(const float4*)(embed + (size_t)cap * EE + e4);
    uint2 h, l;
    split2(val.x, val.y, h.x, l.x);
    split2(val.z, val.w, h.y, l.y);
    ((uint2*)g_embH)[((size_t)m * EE + e4) >> 2] = h;
    ((uint2*)g_embL)[((size_t)m * EE + e4) >> 2] = l;
}

// ---------------------------------------------------------------------------
// mma.sync bf16x3 GEMM for gbias / gx (BM=64, BN=128, 2-stage). Proven config.
template<int MODE>
__global__ __launch_bounds__(256) void k_mm(
    const bf* __restrict__ AH, const bf* __restrict__ AL, int lda,
    const bf* __restrict__ BH, const bf* __restrict__ BL, int ldb,
    float* __restrict__ C, int ldc, int K,
    const float* __restrict__ bias1, const float* __restrict__ bias2,
    const float* __restrict__ addM)
{
    __shared__ unsigned AsH[2][64][12], AsL[2][64][12];
    __shared__ unsigned BsH[2][128][12], BsL[2][128][12];
    const int tid = threadIdx.x;
    const int wid = tid >> 5, lane = tid & 31, g = lane >> 2, tig = lane & 3;
    const int wm = (wid & 1) * 32, wn = (wid >> 1) * 32;
    const int bm = blockIdx.y * 64, bn = blockIdx.x * 128;

    const int arow = tid >> 2, asel = (tid >> 1) & 1, achk = tid & 1;
    const bf* aSrc = (asel ? AL : AH) + (size_t)(bm + arow) * lda + achk * 8;
    unsigned aD[2] = { s2u(&(asel ? AsL : AsH)[0][arow][achk * 4]),
                       s2u(&(asel ? AsL : AsH)[1][arow][achk * 4]) };
    const int b0r = tid >> 2, b0s = (tid >> 1) & 1, b0c = tid & 1;
    const int id1 = tid + 256;
    const int b1r = id1 >> 2, b1s = (id1 >> 1) & 1, b1c = id1 & 1;
    const bf* bSrc0 = (b0s ? BL : BH) + (size_t)(bn + b0r) * ldb + b0c * 8;
    const bf* bSrc1 = (b1s ? BL : BH) + (size_t)(bn + b1r) * ldb + b1c * 8;
    unsigned b0D[2] = { s2u(&(b0s ? BsL : BsH)[0][b0r][b0c * 4]),
                        s2u(&(b0s ? BsL : BsH)[1][b0r][b0c * 4]) };
    unsigned b1D[2] = { s2u(&(b1s ? BsL : BsH)[0][b1r][b1c * 4]),
                        s2u(&(b1s ? BsL : BsH)[1][b1r][b1c * 4]) };

    float acc[2][4][4] = {};
    CP16(aD[0], aSrc); CP16(b0D[0], bSrc0); CP16(b1D[0], bSrc1); CP_COMMIT();

    const int KT = K >> 4;
    for (int kt = 0; kt < KT; kt++) {
        const int cur = kt & 1, nxt = cur ^ 1;
        CP_WAIT0();
        __syncthreads();
        if (kt + 1 < KT) {
            CP16(aD[nxt], aSrc + (kt + 1) * 16);
            CP16(b0D[nxt], bSrc0 + (kt + 1) * 16);
            CP16(b1D[nxt], bSrc1 + (kt + 1) * 16);
            CP_COMMIT();
        }
        unsigned afH[2][4], afL[2][4], bfH[4][2], bfL[4][2];
#pragma unroll
        for (int mt = 0; mt < 2; mt++) {
            int r = wm + mt * 16 + g;
            afH[mt][0] = AsH[cur][r][tig];     afH[mt][1] = AsH[cur][r + 8][tig];
            afH[mt][2] = AsH[cur][r][tig + 4]; afH[mt][3] = AsH[cur][r + 8][tig + 4];
            afL[mt][0] = AsL[cur][r][tig];     afL[mt][1] = AsL[cur][r + 8][tig];
            afL[mt][2] = AsL[cur][r][tig + 4]; afL[mt][3] = AsL[cur][r + 8][tig + 4];
        }
#pragma unroll
        for (int nt = 0; nt < 4; nt++) {
            int n = wn + nt * 8 + g;
            bfH[nt][0] = BsH[cur][n][tig]; bfH[nt][1] = BsH[cur][n][tig + 4];
            bfL[nt][0] = BsL[cur][n][tig]; bfL[nt][1] = BsL[cur][n][tig + 4];
        }
#pragma unroll
        for (int mt = 0; mt < 2; mt++)
#pragma unroll
            for (int nt = 0; nt < 4; nt++) {
                mma_bf16(acc[mt][nt], afL[mt], bfH[nt]);
                mma_bf16(acc[mt][nt], afH[mt], bfL[nt]);
                mma_bf16(acc[mt][nt], afH[mt], bfH[nt]);
            }
    }

#pragma unroll
    for (int mt = 0; mt < 2; mt++) {
#pragma unroll
        for (int nt = 0; nt < 4; nt++) {
            int r0 = bm + wm + mt * 16 + g, r1 = r0 + 8;
            int n0 = bn + wn + nt * 8 + 2 * tig;
            float2 v01 = make_float2(acc[mt][nt][0], acc[mt][nt][1]);
            float2 v23 = make_float2(acc[mt][nt][2], acc[mt][nt][3]);
            if (MODE == 0) {
                float2 x = *(const float2*)(bias1 + n0);
                float2 y = *(const float2*)(bias2 + n0);
                v01.x += x.x + y.x; v01.y += x.y + y.y;
                v23.x += x.x + y.x; v23.y += x.y + y.y;
            }
            if (MODE == 1) {
                float2 x = *(const float2*)(addM + (size_t)(r0 & 63) * GG + n0);
                float2 y = *(const float2*)(addM + (size_t)(r1 & 63) * GG + n0);
                v01.x += x.x; v01.y += x.y;
                v23.x += y.x; v23.y += y.y;
            }
            *(float2*)(C + (size_t)r0 * ldc + n0) = v01;
            *(float2*)(C + (size_t)r1 * ldc + n0) = v23;
        }
    }
}

// ---------------------------------------------------------------------------
// Recurrent step: gates(64x32) = h(t-1) @ W_hh perm, fused LSTM pointwise.
__global__ __launch_bounds__(256) void k_step(const bf* __restrict__ AH,
                                              const bf* __restrict__ AL, int t) {
    __shared__ unsigned AsH[2][64][12], AsL[2][64][12];
    __shared__ unsigned BsH[2][32][12], BsL[2][32][12];
    __shared__ float sg[64][33];
    const int tid = threadIdx.x;
    const int wid = tid >> 5, lane = tid & 31, g = lane >> 2, tig = lane & 3;
    const int wm = (wid & 1) * 32, wn = (wid >> 1) * 8;
    const int jj0 = blockIdx.x * 8;

    const int arow = tid >> 2, asel = (tid >> 1) & 1, achk = tid & 1;
    const bf* aSrc = (asel ? AL : AH) + (size_t)arow * HH + achk * 8;
    unsigned aD[2] = { s2u(&(asel ? AsL : AsH)[0][arow][achk * 4]),
                       s2u(&(asel ? AsL : AsH)[1][arow][achk * 4]) };
    const bf* bSrc = nullptr;
    unsigned bD[2] = {0, 0};
    if (tid < 128) {
        int br = tid >> 2, bs = (tid >> 1) & 1, bc = tid & 1;
        int wrow = (br >> 3) * HH + jj0 + (br & 7);
        bSrc = (bs ? g_WhhL : g_WhhH) + (size_t)wrow * HH + bc * 8;
        bD[0] = s2u(&(bs ? BsL : BsH)[0][br][bc * 4]);
        bD[1] = s2u(&(bs ? BsL : BsH)[1][br][bc * 4]);
    }

    float acc[2][4] = {};
    CP16(aD[0], aSrc);
    if (tid < 128) CP16(bD[0], bSrc);
    CP_COMMIT();

    const int KT = HH >> 4;
    for (int kt = 0; kt < KT; kt++) {
        const int cur = kt & 1, nxt = cur ^ 1;
        CP_WAIT0();
        __syncthreads();
        if (kt + 1 < KT) {
            CP16(aD[nxt], aSrc + (kt + 1) * 16);
            if (tid < 128) CP16(bD[nxt], bSrc + (kt + 1) * 16);
            CP_COMMIT();
        }
        unsigned afH[2][4], afL[2][4], bfH[2], bfL[2];
#pragma unroll
        for (int mt = 0; mt < 2; mt++) {
            int r = wm + mt * 16 + g;
            afH[mt][0] = AsH[cur][r][tig];     afH[mt][1] = AsH[cur][r + 8][tig];
            afH[mt][2] = AsH[cur][r][tig + 4]; afH[mt][3] = AsH[cur][r + 8][tig + 4];
            afL[mt][0] = AsL[cur][r][tig];     afL[mt][1] = AsL[cur][r + 8][tig];
            afL[mt][2] = AsL[cur][r][tig + 4]; afL[mt][3] = AsL[cur][r + 8][tig + 4];
        }
        int n = wn + g;
        bfH[0] = BsH[cur][n][tig]; bfH[1] = BsH[cur][n][tig + 4];
        bfL[0] = BsL[cur][n][tig]; bfL[1] = BsL[cur][n][tig + 4];
#pragma unroll
        for (int mt = 0; mt < 2; mt++) {
            mma_bf16(acc[mt], afL[mt], bfH);
            mma_bf16(acc[mt], afH[mt], bfL);
            mma_bf16(acc[mt], afH[mt], bfH);
        }
    }

#pragma unroll
    for (int mt = 0; mt < 2; mt++)
#pragma unroll
        for (int q = 0; q < 4; q++) {
            int r = wm + mt * 16 + g + ((q >> 1) * 8);
            int j = wn + 2 * tig + (q & 1);
            sg[r][j] = acc[mt][q];
        }
    __syncthreads();

    const float* __restrict__ gx = g_gx + (size_t)t * 64 * GG;
    for (int u = tid; u < 512; u += 256) {
        int b = u >> 3, hh = u & 7;
        size_t gbase = (size_t)b * GG + jj0 + hh;
        float gi = sg[b][0 * 8 + hh] + gx[gbase];
        float gf = sg[b][1 * 8 + hh] + gx[gbase + HH];
        float gg = sg[b][2 * 8 + hh] + gx[gbase + 2 * HH];
        float go = sg[b][3 * 8 + hh] + gx[gbase + 3 * HH];
        int ci = b * HH + jj0 + hh;
        float cOld = g_c[ci];
        float si = 1.f / (1.f + expf(-gi));
        float sf = 1.f / (1.f + expf(-gf));
        float so = 1.f / (1.f + expf(-go));
        float cN = sf * cOld + si * tanhf(gg);
        float hN = so * tanhf(cN);
        g_c[ci] = cN;
        size_t hidx = ((size_t)t * 64 + b) * HH + jj0 + hh;
        bf hb = __float2bfloat16(hN);
        g_hsH[hidx] = hb;
        g_hsL[hidx] = __float2bfloat16(hN - __bfloat162float(hb));
    }
}

// ---------------------------------------------------------------------------
// Logits GEMM: BM=128, BN=128, BK=16, 8 warps (4 M x 2 N), warp tile 32x64.
// 3-stage cp.async, 2 CTAs/SM (reg cap 128 via launch_bounds).
// Stage layout (words): AH[128][12] @0 | AL @1536 | BH[128][12] @3072 | BL @4608
#define LG_STG 6144                  // words per stage (24 KB)
#define SMEM_LG3 (3 * LG_STG * 4)    // 72 KB

__global__ __launch_bounds__(256, 2) void k_logits3(const float* __restrict__ lin_b,
                                                    float* __restrict__ out) {
    extern __shared__ unsigned sm[];
    const int tid = threadIdx.x;
    const int wid = tid >> 5, lane = tid & 31, g = lane >> 2, tig = lane & 3;
    const int wm = (wid & 3) * 32, wn = (wid >> 2) * 64;
    const int bm = blockIdx.x * 128, bn = blockIdx.y * 128;

    // copy tasks: 1024 16B chunks / 256 threads = 4 each
    const bf* csrc[4];
    int cword[4];
#pragma unroll
    for (int q = 0; q < 4; q++) {
        int i = tid + q * 256;
        int row = (i >> 2) & 127, sel = (i >> 1) & 1, chunk = i & 1;
        if (i < 512) {
            csrc[q] = (sel ? g_hsL : g_hsH) + (size_t)(bm + row) * HH + chunk * 8;
            cword[q] = sel * 1536 + row * 12 + chunk * 4;
        } else {
            csrc[q] = (sel ? g_linWL : g_linWH) + (size_t)(bn + row) * HH + chunk * 8;
            cword[q] = 3072 + sel * 1536 + row * 12 + chunk * 4;
        }
    }

    float acc[2][8][4] = {};

    // prologue: slabs 0, 1
#pragma unroll
    for (int s = 0; s < 2; s++) {
#pragma unroll
        for (int q = 0; q < 4; q++)
            CP16(s2u(&sm[s * LG_STG + cword[q]]), csrc[q] + s * 16);
        CP_COMMIT();
    }

    const int KT = HH >> 4;   // 64
    int buf = 0;
    for (int kt = 0; kt < KT; kt++) {
        CP_WAIT1();
        __syncthreads();      // slab kt visible; all warps done with buf(kt-1)
        if (kt + 2 < KT) {
            int s = (buf + 2) % 3;
#pragma unroll
            for (int q = 0; q < 4; q++)
                CP16(s2u(&sm[s * LG_STG + cword[q]]), csrc[q] + (kt + 2) * 16);
            CP_COMMIT();
        } else {
            CP_COMMIT();      // keep group count uniform for WAIT1
        }

        const unsigned* AHs = sm + buf * LG_STG;
        const unsigned* ALs = AHs + 1536;
        const unsigned* BHs = AHs + 3072;
        const unsigned* BLs = AHs + 4608;

        unsigned aH[2][4], aL[2][4];
#pragma unroll
        for (int mt = 0; mt < 2; mt++) {
            int r = (wm + mt * 16 + g) * 12;
            aH[mt][0] = AHs[r + tig];     aH[mt][1] = AHs[r + 96 + tig];
            aH[mt][2] = AHs[r + tig + 4]; aH[mt][3] = AHs[r + 96 + tig + 4];
            aL[mt][0] = ALs[r + tig];     aL[mt][1] = ALs[r + 96 + tig];
            aL[mt][2] = ALs[r + tig + 4]; aL[mt][3] = ALs[r + 96 + tig + 4];
        }
#pragma unroll
        for (int nt = 0; nt < 8; nt++) {
            int n = (wn + nt * 8 + g) * 12;
            unsigned bH[2], bL[2];
            bH[0] = BHs[n + tig]; bH[1] = BHs[n + tig + 4];
            bL[0] = BLs[n + tig]; bL[1] = BLs[n + tig + 4];
#pragma unroll
            for (int mt = 0; mt < 2; mt++) {
                mma_bf16(acc[mt][nt], aL[mt], bH);
                mma_bf16(acc[mt][nt], aH[mt], bL);
                mma_bf16(acc[mt][nt], aH[mt], bH);
            }
        }
        buf = (buf + 1) % 3;
    }

#pragma unroll
    for (int mt = 0; mt < 2; mt++) {
#pragma unroll
        for (int q2 = 0; q2 < 2; q2++) {
            int m = bm + wm + mt * 16 + g + q2 * 8;
            if (m >= TT * BB) continue;
            float* orow = out + (size_t)m * VV + bn;
#pragma unroll
            for (int nt = 0; nt < 8; nt++) {
                int n0 = wn + nt * 8 + 2 * tig;
                float2 bb = *(const float2*)(lin_b + bn + n0);
                float2 v = make_float2(acc[mt][nt][q2 * 2] + bb.x,
                                       acc[mt][nt][q2 * 2 + 1] + bb.y);
                *(float2*)(orow + n0) = v;
            }
        }
    }
}

// ---------------------------------------------------------------------------
extern "C" void kernel_launch(void* const* d_in, const int* in_sizes, int n_in,
                              void* d_out, int out_size) {
    const float* features = (const float*)d_in[0];
    const int*   captions = (const int*)d_in[1];
    const float* embed    = (const float*)d_in[3];
    const float* W_ih     = (const float*)d_in[4];
    const float* W_hh     = (const float*)d_in[5];
    const float* b_ih     = (const float*)d_in[6];
    const float* b_hh     = (const float*)d_in[7];
    const float* lin_W    = (const float*)d_in[10];
    const float* lin_b    = (const float*)d_in[11];
    float* out = (float*)d_out;

    bf *p_linWH, *p_linWL, *p_WihH, *p_WihL, *p_WhhH, *p_WhhL;
    bf *p_ctxH, *p_ctxL, *p_embH, *p_embL, *p_hsH, *p_hsL, *p_h0H, *p_h0L;
    float *p_gbias, *p_gx;
    cudaGetSymbolAddress((void**)&p_linWH, g_linWH);
    cudaGetSymbolAddress((void**)&p_linWL, g_linWL);
    cudaGetSymbolAddress((void**)&p_WihH, g_WihH);
    cudaGetSymbolAddress((void**)&p_WihL, g_WihL);
    cudaGetSymbolAddress((void**)&p_WhhH, g_WhhH);
    cudaGetSymbolAddress((void**)&p_WhhL, g_WhhL);
    cudaGetSymbolAddress((void**)&p_ctxH, g_ctxH);
    cudaGetSymbolAddress((void**)&p_ctxL, g_ctxL);
    cudaGetSymbolAddress((void**)&p_embH, g_embH);
    cudaGetSymbolAddress((void**)&p_embL, g_embL);
    cudaGetSymbolAddress((void**)&p_hsH, g_hsH);
    cudaGetSymbolAddress((void**)&p_hsL, g_hsL);
    cudaGetSymbolAddress((void**)&p_h0H, g_h0H);
    cudaGetSymbolAddress((void**)&p_h0L, g_h0L);
    cudaGetSymbolAddress((void**)&p_gbias, g_gbias);
    cudaGetSymbolAddress((void**)&p_gx, g_gx);

    cudaFuncSetAttribute(k_logits3, cudaFuncAttributeMaxDynamicSharedMemorySize, SMEM_LG3);

    k_init<<<(BB * HH + 255) / 256, 256>>>();
    int n4;
    n4 = VV * HH / 4;
    k_conv<<<(n4 + 255) / 256, 256>>>((const float4*)lin_W, (uint2*)p_linWH, (uint2*)p_linWL, n4);
    n4 = GG * 1536 / 4;
    k_conv<<<(n4 + 255) / 256, 256>>>((const float4*)W_ih, (uint2*)p_WihH, (uint2*)p_WihL, n4);
    n4 = GG * HH / 4;
    k_conv<<<(n4 + 255) / 256, 256>>>((const float4*)W_hh, (uint2*)p_WhhH, (uint2*)p_WhhL, n4);
    k_ctx<<<BB, 256>>>(features);
    k_emb<<<(TT * BB * EE / 4 + 255) / 256, 256>>>(embed, captions);
    k_mm<0><<<dim3(GG / 128, 1), 256>>>(p_ctxH, p_ctxL, HH,
                                        p_WihH + 512, p_WihL + 512, 1536,
                                        p_gbias, GG, HH, b_ih, b_hh, nullptr);
    k_mm<1><<<dim3(GG / 128, TT), 256>>>(p_embH, p_embL, EE,
                                         p_WihH, p_WihL, 1536,
                                         p_gx, GG, EE, nullptr, nullptr, p_gbias);
    for (int t = 0; t < TT; t++) {
        const bf* AH = t ? p_hsH + (size_t)(t - 1) * BB * HH : p_h0H;
        const bf* AL = t ? p_hsL + (size_t)(t - 1) * BB * HH : p_h0L;
        k_step<<<128, 256>>>(AH, AL, t);
    }
    // grid: x = M tiles (16), y = N tiles (250) -> wave shares lin_W tiles in L2
    k_logits3<<<dim3(MPAD / 128, VV / 128), 256, SMEM_LG3>>>(lin_b, out);
}